// round 16
// baseline (speedup 1.0000x reference)
#include <cuda_runtime.h>
#include <cuda_bf16.h>
#include <cstdint>
#include <math.h>

#define BB 2
#define NN 4096
#define HH 64
#define INDIM 32
#define OUTDIM 8
#define ROWS (BB*NN)
#define NSPLIT 4

// ---------------- device scratch (static, allocation-free) ----------------
__device__ __align__(16) __nv_bfloat16 g_qnb[3][ROWS*HH];     // normalized queries (bf16)
__device__ __align__(16) __nv_bfloat16 g_knb[6][ROWS*HH];     // normalized keys (bf16)
__device__ __align__(16) __nv_bfloat16 g_v[3][ROWS*HH];       // h values as bf16
// Permuted packed masks: word w = chunk(128 floats)*4 + component k.
// col p: word = (p>>7)*4 + (p&3), bit = (p&127)>>2.
__device__ __align__(16) unsigned int  g_mbits[6][NN/32][NN]; // [e][word][row]
__device__ float g_inv[6][NN];                                // 1/rowcount per edge
__device__ __align__(16) float g_acc[3][ROWS*HH];             // attention result (fp32)

__device__ __forceinline__ uint32_t smem_u32(const void* p) {
    uint32_t a;
    asm("{ .reg .u64 t; cvta.to.shared.u64 t, %1; cvt.u32.u64 %0, t; }" : "=r"(a) : "l"(p));
    return a;
}

// ============================================================
// Kernel A1 (main stream): mask bit-pack, ALL 6 edges, no smem.
// Warp/row; 8 coalesced float4 loads batched (MLP~8), then ballots.
// Runs as a pure DRAM stream (measured 76% DRAM standalone in R13).
// ============================================================
__global__ void __launch_bounds__(256) pack_all_kernel(
        const float* __restrict__ m00, const float* __restrict__ m20,
        const float* __restrict__ m01, const float* __restrict__ m11,
        const float* __restrict__ m12, const float* __restrict__ m22) {
    const float* tab[6] = {m00, m20, m01, m11, m12, m22};
    int blk = blockIdx.x;
    int tid = threadIdx.x;
    int e = blk >> 9;                              // 6 x 512 blocks
    int row = ((blk & 511) << 3) + (tid >> 5);
    int lane = tid & 31;
    const float4* mr4 = (const float4*)(tab[e] + (size_t)row * NN);
    int cnt = 0;
#pragma unroll
    for (int gq = 0; gq < 4; gq++) {
        float4 v[8];
#pragma unroll
        for (int u = 0; u < 8; u++)
            v[u] = mr4[(gq * 8 + u) * 32 + lane];
#pragma unroll
        for (int u = 0; u < 8; u++) {
            int c = gq * 8 + u;
            unsigned b0 = __ballot_sync(0xffffffffu, v[u].x > 0.5f);
            unsigned b1 = __ballot_sync(0xffffffffu, v[u].y > 0.5f);
            unsigned b2 = __ballot_sync(0xffffffffu, v[u].z > 0.5f);
            unsigned b3 = __ballot_sync(0xffffffffu, v[u].w > 0.5f);
            if (lane < 4) {
                unsigned bb = (lane == 0) ? b0 : (lane == 1) ? b1
                             : (lane == 2) ? b2 : b3;
                g_mbits[e][c * 4 + lane][row] = bb;
            }
            cnt += __popc(b0) + __popc(b1) + __popc(b2) + __popc(b3);
        }
    }
    if (lane == 0) g_inv[e][row] = 1.0f / (float)cnt;
}

// ============================================================
// Kernel A2 (side stream): q/k projection + L2 norm, h->bf16 conv + zero acc.
// FMA-bound, ~28 MB of traffic — overlaps the pack's DRAM stream.
//   [0, 1152)      proj jobs (9 x 128 blocks)
//   [1152, 2688)   conv jobs (3 x 512 blocks)
// ============================================================
#define PJ_PROJ 1152
#define PJ_CONV 1536

__global__ void __launch_bounds__(256) projconv_kernel(
        const float* __restrict__ h0, const float* __restrict__ h1,
        const float* __restrict__ h2,
        const float* __restrict__ Wq, const float* __restrict__ Wk) {
    __shared__ float sH[64][65];
    __shared__ float sW[64][65];
    int blk = blockIdx.x;
    int tid = threadIdx.x;

    if (blk < PJ_PROJ) {
        int job = blk >> 7;
        int row0 = (blk & 127) * 64;
        const float* hs; const float* W; __nv_bfloat16* dst;
        if (job < 3) {
            hs = (job == 0) ? h0 : (job == 1 ? h1 : h2);
            W = Wq + job * HH * HH;
            dst = g_qnb[job];
        } else {
            int e = job - 3;
            int pred = (e == 0 || e == 2) ? 0 : ((e == 3 || e == 4) ? 1 : 2);
            hs = (pred == 0) ? h0 : (pred == 1 ? h1 : h2);
            W = Wk + e * HH * HH;
            dst = g_knb[e];
        }
        for (int i = tid; i < 64 * 64; i += 256) {
            int r = i >> 6, c = i & 63;
            sH[r][c] = hs[(size_t)(row0 + r) * HH + c];
            sW[r][c] = W[i];
        }
        __syncthreads();
        int ty = tid >> 4, tx = tid & 15;
        float acc[4][4] = {};
#pragma unroll 8
        for (int k = 0; k < 64; k++) {
            float a[4], bv[4];
#pragma unroll
            for (int i = 0; i < 4; i++) a[i] = sH[ty * 4 + i][k];
#pragma unroll
            for (int j = 0; j < 4; j++) bv[j] = sW[tx * 4 + j][k];
#pragma unroll
            for (int i = 0; i < 4; i++)
#pragma unroll
                for (int j = 0; j < 4; j++)
                    acc[i][j] = fmaf(a[i], bv[j], acc[i][j]);
        }
        float ss[4];
#pragma unroll
        for (int i = 0; i < 4; i++)
            ss[i] = acc[i][0]*acc[i][0] + acc[i][1]*acc[i][1]
                  + acc[i][2]*acc[i][2] + acc[i][3]*acc[i][3];
#pragma unroll
        for (int off = 8; off >= 1; off >>= 1)
#pragma unroll
            for (int i = 0; i < 4; i++)
                ss[i] += __shfl_xor_sync(0xffffffffu, ss[i], off);
#pragma unroll
        for (int i = 0; i < 4; i++) {
            float inv = rsqrtf(ss[i]);
#pragma unroll
            for (int j = 0; j < 4; j++)
                dst[(size_t)(row0 + ty * 4 + i) * HH + tx * 4 + j] =
                    __float2bfloat16(acc[i][j] * inv);
        }
        return;
    }
    {
        int p = blk - PJ_PROJ;
        int tt = p >> 9;
        int idx = ((p & 511) << 8) + tid;
        const float* src = (tt == 0) ? h0 : (tt == 1 ? h1 : h2);
        __nv_bfloat16* dst = g_v[tt];
        float4 v = ((const float4*)src)[idx];
        ((__nv_bfloat162*)dst)[idx * 2]     = __floats2bfloat162_rn(v.x, v.y);
        ((__nv_bfloat162*)dst)[idx * 2 + 1] = __floats2bfloat162_rn(v.z, v.w);
        ((float4*)g_acc[tt])[idx] = make_float4(0.f, 0.f, 0.f, 0.f);
    }
}

// ============================================================
// Kernel B: masked cosine attention (R12-exact, unchanged)
// ============================================================
#define LDS_PAD 72
#define KVOFF_H (128*LDS_PAD)
#define BUF_STRIDE_H (2*64*LDS_PAD)
#define ATTN_SMEM ((KVOFF_H + 3*BUF_STRIDE_H) * 2)   // 73728 B

#define LDSM_X4(r0,r1,r2,r3,addr) \
    asm volatile("ldmatrix.sync.aligned.m8n8.x4.shared.b16 {%0,%1,%2,%3}, [%4];" \
        : "=r"(r0), "=r"(r1), "=r"(r2), "=r"(r3) : "r"(addr))
#define LDSM_X4_T(r0,r1,r2,r3,addr) \
    asm volatile("ldmatrix.sync.aligned.m8n8.x4.trans.shared.b16 {%0,%1,%2,%3}, [%4];" \
        : "=r"(r0), "=r"(r1), "=r"(r2), "=r"(r3) : "r"(addr))
#define MMA16816(c, a, b0, b1) \
    asm volatile("mma.sync.aligned.m16n8k16.row.col.f32.bf16.bf16.f32 " \
        "{%0,%1,%2,%3}, {%4,%5,%6,%7}, {%8,%9}, {%0,%1,%2,%3};" \
        : "+f"((c)[0]), "+f"((c)[1]), "+f"((c)[2]), "+f"((c)[3]) \
        : "r"((a)[0]), "r"((a)[1]), "r"((a)[2]), "r"((a)[3]), "r"(b0), "r"(b1))
#define CP_ASYNC16(dst, src) \
    asm volatile("cp.async.cg.shared.global [%0], [%1], 16;" :: "r"(dst), "l"(src))
#define CP_COMMIT() asm volatile("cp.async.commit_group;" ::: "memory")
#define CP_WAIT(n)  asm volatile("cp.async.wait_group %0;" :: "n"(n) : "memory")

#define VPRED(e) ((0x948 >> (2 * (e))) & 3)   // {0,2,0,1,1,2}

__global__ void __launch_bounds__(128, 3) attn_mma_kernel() {
    extern __shared__ __align__(16) __nv_bfloat16 smh[];
    int tid = threadIdx.x, warp = tid >> 5, lane = tid & 31;
    int g = lane >> 2, tig = lane & 3;
    int t = blockIdx.z >> 1, b = blockIdx.z & 1;
    int split = blockIdx.y;
    int row0 = blockIdx.x * 128;

    uint32_t sQb = smem_u32(smh);
    uint32_t sKVb = sQb + KVOFF_H * 2;

    const __nv_bfloat16* qg = g_qnb[t] + ((size_t)b * NN + row0) * HH;
#pragma unroll
    for (int i = 0; i < 8; i++) {
        int idx = i * 128 + tid;
        int r = idx >> 3, c = idx & 7;
        *(uint4*)&smh[r * LDS_PAD + c * 8] = *(const uint4*)&qg[r * HH + c * 8];
    }
    __syncthreads();

    uint32_t qa[2][4][4];
    {
        int qcol = (lane >> 4) << 3;
#pragma unroll
        for (int rb = 0; rb < 2; rb++) {
            int qrow = warp * 32 + rb * 16 + (lane & 15);
#pragma unroll
            for (int kc = 0; kc < 4; kc++) {
                uint32_t addr = sQb + (uint32_t)(qrow * LDS_PAD + kc * 16 + qcol) * 2;
                LDSM_X4(qa[rb][kc][0], qa[rb][kc][1], qa[rb][kc][2], qa[rb][kc][3], addr);
            }
        }
    }

    int rowA[2], rowB[2];
#pragma unroll
    for (int rb = 0; rb < 2; rb++) {
        rowA[rb] = row0 + warp * 32 + rb * 16 + g;
        rowB[rb] = rowA[rb] + 8;
    }

    float invA[2][2], invB[2][2];
#pragma unroll
    for (int eh = 0; eh < 2; eh++) {
        int e = 2 * t + eh;
#pragma unroll
        for (int rb = 0; rb < 2; rb++) {
            invA[eh][rb] = g_inv[e][rowA[rb]];
            invB[eh][rb] = g_inv[e][rowB[rb]];
        }
    }

    auto stage = [&](int tile, int buf) {
        int e2 = 2 * t + (tile >> 4);
        size_t toff = (size_t)b * NN * HH + (size_t)(split * 16 + (tile & 15)) * 64 * HH;
        const __nv_bfloat16* kg = g_knb[e2] + toff;
        const __nv_bfloat16* vg = g_v[VPRED(e2)] + toff;
        uint32_t kb = sKVb + (uint32_t)buf * (BUF_STRIDE_H * 2);
        uint32_t vb = kb + (uint32_t)(64 * LDS_PAD * 2);
#pragma unroll
        for (int i = 0; i < 4; i++) {
            int idx = i * 128 + tid;
            int r = idx >> 3, c = (idx & 7) * 8;
            uint32_t so = (uint32_t)(r * LDS_PAD + c) * 2;
            CP_ASYNC16(kb + so, kg + r * HH + c);
            CP_ASYNC16(vb + so, vg + r * HH + c);
        }
        CP_COMMIT();
    };

    stage(0, 0);
    stage(1, 1);

    float o[2][8][4] = {};
    int k0 = (tig & 1) * 2;
    int shbase0 = tig >> 1;

    for (int it = 0; it < 32; it++) {
        int eh = it >> 4;
        int e = 2 * t + eh;
        int kt = split * 16 + (it & 15);
        int c4 = (kt >> 1) * 4;
        int shb = shbase0 + ((kt & 1) << 4);
        uint32_t mEA[2], mOA[2], mEB[2], mOB[2];
#pragma unroll
        for (int rb = 0; rb < 2; rb++) {
            mEA[rb] = g_mbits[e][c4 + k0][rowA[rb]];
            mOA[rb] = g_mbits[e][c4 + k0 + 1][rowA[rb]];
            mEB[rb] = g_mbits[e][c4 + k0][rowB[rb]];
            mOB[rb] = g_mbits[e][c4 + k0 + 1][rowB[rb]];
        }

        if (it < 31) CP_WAIT(1); else CP_WAIT(0);
        __syncthreads();
        if (it + 2 < 32) stage(it + 2, (it + 2) % 3);

        uint32_t kb = sKVb + (uint32_t)(it % 3) * (BUF_STRIDE_H * 2);
        uint32_t vb = kb + (uint32_t)(64 * LDS_PAD * 2);

        int krow_off = ((lane >> 4) << 3) + (lane & 7);
        int kcol_off = ((lane >> 3) & 1) << 3;

#pragma unroll
        for (int jph = 0; jph < 2; jph++) {
            uint32_t pa[2][2][4];
#pragma unroll
            for (int jj2 = 0; jj2 < 2; jj2++) {
                int jp = 2 * jph + jj2;
                float s2[2][2][4] = {};
#pragma unroll
                for (int kc = 0; kc < 4; kc++) {
                    uint32_t b0, b1, b2, b3;
                    uint32_t addr = kb + (uint32_t)((16 * jp + krow_off) * LDS_PAD
                                                     + kc * 16 + kcol_off) * 2;
                    LDSM_X4(b0, b1, b2, b3, addr);
#pragma unroll
                    for (int rb = 0; rb < 2; rb++) {
                        MMA16816(s2[rb][0], qa[rb][kc], b0, b1);
                        MMA16816(s2[rb][1], qa[rb][kc], b2, b3);
                    }
                }
#pragma unroll
                for (int rb = 0; rb < 2; rb++) {
#pragma unroll
                    for (int jj = 0; jj < 2; jj++) {
                        int j = 2 * jp + jj;
                        int sh = shb + 2 * j;
                        float f0 = ((mEA[rb] >> sh) & 1u) ? s2[rb][jj][0] * invA[eh][rb] : 0.0f;
                        float f1 = ((mOA[rb] >> sh) & 1u) ? s2[rb][jj][1] * invA[eh][rb] : 0.0f;
                        float f2 = ((mEB[rb] >> sh) & 1u) ? s2[rb][jj][2] * invB[eh][rb] : 0.0f;
                        float f3 = ((mOB[rb] >> sh) & 1u) ? s2[rb][jj][3] * invB[eh][rb] : 0.0f;
                        uint32_t p01, p23;
                        asm("cvt.rn.bf16x2.f32 %0, %1, %2;" : "=r"(p01) : "f"(f1), "f"(f0));
                        asm("cvt.rn.bf16x2.f32 %0, %1, %2;" : "=r"(p23) : "f"(f3), "f"(f2));
                        pa[rb][jj2][jj * 2]     = p01;
                        pa[rb][jj2][jj * 2 + 1] = p23;
                    }
                }
            }
#pragma unroll
            for (int nt = 0; nt < 8; nt++) {
                uint32_t b0, b1, b2, b3;
                uint32_t addr = vb + (uint32_t)((32 * jph + lane) * LDS_PAD + nt * 8) * 2;
                LDSM_X4_T(b0, b1, b2, b3, addr);
#pragma unroll
                for (int rb = 0; rb < 2; rb++) {
                    MMA16816(o[rb][nt], pa[rb][0], b0, b1);
                    MMA16816(o[rb][nt], pa[rb][1], b2, b3);
                }
            }
        }
    }

    float* dst = g_acc[t] + (size_t)b * NN * HH;
#pragma unroll
    for (int rb = 0; rb < 2; rb++) {
#pragma unroll
        for (int nt = 0; nt < 8; nt++) {
            int col = nt * 8 + 2 * tig;
            atomicAdd(&dst[(size_t)rowA[rb] * HH + col],     o[rb][nt][0]);
            atomicAdd(&dst[(size_t)rowA[rb] * HH + col + 1], o[rb][nt][1]);
            atomicAdd(&dst[(size_t)rowB[rb] * HH + col],     o[rb][nt][2]);
            atomicAdd(&dst[(size_t)rowB[rb] * HH + col + 1], o[rb][nt][3]);
        }
    }
}

// ============================================================
// Kernel C: gated Euler update + outputs (fp32, unchanged)
// ============================================================
__global__ void update_kernel(const float* __restrict__ x0,
                              const float* __restrict__ h0,
                              const float* __restrict__ h1,
                              const float* __restrict__ h2,
                              const float* __restrict__ Wsu0,
                              const float* __restrict__ Wsu12,
                              const float* __restrict__ Wdt,
                              const float* __restrict__ bdt,
                              const float* __restrict__ stepp,
                              const float* __restrict__ oscale,
                              float* __restrict__ out2,
                              float* __restrict__ outh0,
                              float* __restrict__ outh1,
                              float* __restrict__ outh2) {
    extern __shared__ float sm[];
    float* sH = sm;               // [64][65]
    float* sW = sm + 64 * 65;     // [64][97]
    float* sA = sW + 64 * 97;     // [64][97]
    int t = blockIdx.y;
    int row0 = blockIdx.x * 64;
    int tid = threadIdx.x, ty = tid >> 4, tx = tid & 15;

    const float* hs = (t == 0) ? h0 : (t == 1 ? h1 : h2);
    float* outh = (t == 0) ? outh0 : (t == 1 ? outh1 : outh2);
    const float* Wd = Wdt + t * HH * HH;

    for (int i = tid; i < 64 * 64; i += 256) {
        int r = i >> 6, c = i & 63;
        sH[r * 65 + c] = hs[(size_t)(row0 + r) * HH + c];
        sW[r * 97 + c] = Wd[i];
    }
    __syncthreads();

    float z[4][4];
#pragma unroll
    for (int j = 0; j < 4; j++) {
        float bj = __ldg(&bdt[t * 64 + tx * 4 + j]);
#pragma unroll
        for (int i = 0; i < 4; i++) z[i][j] = bj;
    }
#pragma unroll 8
    for (int k = 0; k < 64; k++) {
        float a[4], bv[4];
#pragma unroll
        for (int i = 0; i < 4; i++) a[i] = sH[(ty * 4 + i) * 65 + k];
#pragma unroll
        for (int j = 0; j < 4; j++) bv[j] = sW[(tx * 4 + j) * 97 + k];
#pragma unroll
        for (int i = 0; i < 4; i++)
#pragma unroll
            for (int j = 0; j < 4; j++)
                z[i][j] = fmaf(a[i], bv[j], z[i][j]);
    }
    float dtv[4][4];
#pragma unroll
    for (int i = 0; i < 4; i++)
#pragma unroll
        for (int j = 0; j < 4; j++)
            dtv[i][j] = 2.0f / (1.0f + expf(-z[i][j])) - 1.0f;
    __syncthreads();

    int Ksu = (t == 0) ? (INDIM + HH) : HH;
    const float* Ws = (t == 0) ? Wsu0 : (Wsu12 + (t - 1) * HH * HH);
    const float* acc = g_acc[t];
    for (int i = tid; i < 64 * Ksu; i += 256) {
        int r = i / Ksu, c = i - r * Ksu;
        sW[r * 97 + c] = Ws[i];
        float av;
        if (t == 0) {
            if (c < INDIM) av = x0[(size_t)(row0 + r) * INDIM + c];
            else           av = acc[(size_t)(row0 + r) * HH + (c - INDIM)];
        } else {
            av = acc[(size_t)(row0 + r) * HH + c];
        }
        sA[r * 97 + c] = av;
    }
    __syncthreads();

    float su[4][4] = {};
#pragma unroll 8
    for (int k = 0; k < Ksu; k++) {
        float a[4], bv[4];
#pragma unroll
        for (int i = 0; i < 4; i++) a[i] = sA[(ty * 4 + i) * 97 + k];
#pragma unroll
        for (int j = 0; j < 4; j++) bv[j] = sW[(tx * 4 + j) * 97 + k];
#pragma unroll
        for (int i = 0; i < 4; i++)
#pragma unroll
            for (int j = 0; j < 4; j++)
                su[i][j] = fmaf(a[i], bv[j], su[i][j]);
    }

    float stepv = *stepp;
    float osc = *oscale;
#pragma unroll
    for (int i = 0; i < 4; i++) {
        int r = row0 + ty * 4 + i;
#pragma unroll
        for (int j = 0; j < 4; j++) {
            int c = tx * 4 + j;
            float hv = sH[(ty * 4 + i) * 65 + c];
            float hn = fmaf(stepv * dtv[i][j], su[i][j], hv);
            outh[(size_t)r * HH + c] = hn;
            if (t == 2 && c < OUTDIM)
                out2[(size_t)r * OUTDIM + c] = osc * hn;
        }
    }
}

// ============================================================
// Stream/event plumbing (ctor-created + warmed; launch-time code is
// allocation-free and capture-safe — validated in R13/R14 benches).
// ============================================================
__global__ void warm_kernel() {}

struct GraphStreams {
    cudaStream_t side = nullptr;
    cudaEvent_t evA = nullptr, evB = nullptr;
    GraphStreams() {
        cudaStreamCreateWithFlags(&side, cudaStreamNonBlocking);
        cudaEventCreateWithFlags(&evA, cudaEventDisableTiming);
        cudaEventCreateWithFlags(&evB, cudaEventDisableTiming);
        warm_kernel<<<1, 32>>>();
        cudaEventRecord(evA, 0);
        cudaStreamWaitEvent(side, evA, 0);
        warm_kernel<<<1, 32, 0, side>>>();
        cudaEventRecord(evB, side);
        cudaStreamWaitEvent(0, evB, 0);
        warm_kernel<<<1, 32>>>();
        cudaDeviceSynchronize();
    }
};
static GraphStreams g_gs;

extern "C" void kernel_launch(void* const* d_in, const int* in_sizes, int n_in,
                              void* d_out, int out_size) {
    const float* x0  = (const float*)d_in[0];
    const float* h0  = (const float*)d_in[1];
    const float* h1  = (const float*)d_in[2];
    const float* h2  = (const float*)d_in[3];
    const float* m00 = (const float*)d_in[4];
    const float* m20 = (const float*)d_in[5];
    const float* m01 = (const float*)d_in[6];
    const float* m11 = (const float*)d_in[7];
    const float* m12 = (const float*)d_in[8];
    const float* m22 = (const float*)d_in[9];
    const float* Wq    = (const float*)d_in[10];
    const float* Wk    = (const float*)d_in[11];
    const float* Wsu0  = (const float*)d_in[12];
    const float* Wsu12 = (const float*)d_in[13];
    const float* Wdt   = (const float*)d_in[14];
    const float* bdt   = (const float*)d_in[15];
    const float* stepp = (const float*)d_in[16];
    const float* oscal = (const float*)d_in[17];

    float* out2 = (float*)d_out;
    float* h0n = out2 + (size_t)BB * NN * OUTDIM;
    float* h1n = h0n + (size_t)BB * NN * HH;
    float* h2n = h1n + (size_t)BB * NN * HH;

    const int UPD_SMEM = (64 * 65 + 2 * 64 * 97) * 4;
    cudaFuncSetAttribute(attn_mma_kernel, cudaFuncAttributeMaxDynamicSharedMemorySize, ATTN_SMEM);
    cudaFuncSetAttribute(update_kernel, cudaFuncAttributeMaxDynamicSharedMemorySize, UPD_SMEM);

    // fork at entry: side stream runs FMA-bound proj+conv while the main
    // stream runs the pure-DRAM mask pack — complementary resources.
    cudaEventRecord(g_gs.evA, 0);
    cudaStreamWaitEvent(g_gs.side, g_gs.evA, 0);
    projconv_kernel<<<PJ_PROJ + PJ_CONV, 256, 0, g_gs.side>>>(h0, h1, h2, Wq, Wk);
    cudaEventRecord(g_gs.evB, g_gs.side);

    pack_all_kernel<<<3072, 256>>>(m00, m20, m01, m11, m12, m22);

    // join: attention needs proj/conv outputs and zeroed g_acc
    cudaStreamWaitEvent(0, g_gs.evB, 0);
    attn_mma_kernel<<<dim3(NN / 128, NSPLIT, 6), 128, ATTN_SMEM>>>();
    update_kernel<<<dim3(ROWS / 64, 3), 256, UPD_SMEM>>>(x0, h0, h1, h2,
                                                         Wsu0, Wsu12, Wdt, bdt,
                                                         stepp, oscal,
                                                         out2, h0n, h1n, h2n);
}

// round 17
// speedup vs baseline: 1.0317x; 1.0317x over previous
#include <cuda_runtime.h>
#include <cuda_bf16.h>
#include <cstdint>
#include <math.h>

#define BB 2
#define NN 4096
#define HH 64
#define INDIM 32
#define OUTDIM 8
#define ROWS (BB*NN)
#define NSPLIT 4

// ---------------- device scratch (static, allocation-free) ----------------
__device__ __align__(16) __nv_bfloat16 g_qnb[3][ROWS*HH];     // normalized queries (bf16)
__device__ __align__(16) __nv_bfloat16 g_knb[6][ROWS*HH];     // normalized keys (bf16)
__device__ __align__(16) __nv_bfloat16 g_v[3][ROWS*HH];       // h values as bf16
// Permuted packed masks: word w = chunk(128 floats)*4 + component k.
// col p: word = (p>>7)*4 + (p&3), bit = (p&127)>>2.
__device__ __align__(16) unsigned int  g_mbits[6][NN/32][NN]; // [e][word][row]
__device__ float g_inv[6][NN];                                // 1/rowcount per edge
__device__ __align__(16) float g_acc[3][ROWS*HH];             // attention result (fp32)

__device__ __forceinline__ uint32_t smem_u32(const void* p) {
    uint32_t a;
    asm("{ .reg .u64 t; cvta.to.shared.u64 t, %1; cvt.u32.u64 %0, t; }" : "=r"(a) : "l"(p));
    return a;
}

// ============================================================
// Kernel A: fused pre-pass (R15-exact: MLP-8 mask pack, no reg cap).
// ============================================================
#define PRE_MASK 3072
#define PRE_PROJ 1152
#define PRE_CONV 1536

__global__ void __launch_bounds__(256) pre_kernel(
        const float* __restrict__ h0, const float* __restrict__ h1,
        const float* __restrict__ h2,
        const float* __restrict__ Wq, const float* __restrict__ Wk,
        const float* __restrict__ m00, const float* __restrict__ m20,
        const float* __restrict__ m01, const float* __restrict__ m11,
        const float* __restrict__ m12, const float* __restrict__ m22) {
    __shared__ float sH[64][65];
    __shared__ float sW[64][65];
    int blk = blockIdx.x;
    int tid = threadIdx.x;

    if (blk < PRE_MASK) {
        const float* tab[6] = {m00, m20, m01, m11, m12, m22};
        int e = blk >> 9;
        int row = ((blk & 511) << 3) + (tid >> 5);
        int lane = tid & 31;
        const float4* mr4 = (const float4*)(tab[e] + (size_t)row * NN);
        int cnt = 0;
#pragma unroll
        for (int gq = 0; gq < 4; gq++) {
            float4 v[8];
#pragma unroll
            for (int u = 0; u < 8; u++)
                v[u] = mr4[(gq * 8 + u) * 32 + lane];
#pragma unroll
            for (int u = 0; u < 8; u++) {
                int c = gq * 8 + u;
                unsigned b0 = __ballot_sync(0xffffffffu, v[u].x > 0.5f);
                unsigned b1 = __ballot_sync(0xffffffffu, v[u].y > 0.5f);
                unsigned b2 = __ballot_sync(0xffffffffu, v[u].z > 0.5f);
                unsigned b3 = __ballot_sync(0xffffffffu, v[u].w > 0.5f);
                if (lane < 4) {
                    unsigned bb = (lane == 0) ? b0 : (lane == 1) ? b1
                                 : (lane == 2) ? b2 : b3;
                    g_mbits[e][c * 4 + lane][row] = bb;
                }
                cnt += __popc(b0) + __popc(b1) + __popc(b2) + __popc(b3);
            }
        }
        if (lane == 0) g_inv[e][row] = 1.0f / (float)cnt;
        return;
    }
    if (blk < PRE_MASK + PRE_PROJ) {
        int p = blk - PRE_MASK;
        int job = p >> 7;
        int row0 = (p & 127) * 64;
        const float* hs; const float* W; __nv_bfloat16* dst;
        if (job < 3) {
            hs = (job == 0) ? h0 : (job == 1 ? h1 : h2);
            W = Wq + job * HH * HH;
            dst = g_qnb[job];
        } else {
            int e = job - 3;
            int pred = (e == 0 || e == 2) ? 0 : ((e == 3 || e == 4) ? 1 : 2);
            hs = (pred == 0) ? h0 : (pred == 1 ? h1 : h2);
            W = Wk + e * HH * HH;
            dst = g_knb[e];
        }
        for (int i = tid; i < 64 * 64; i += 256) {
            int r = i >> 6, c = i & 63;
            sH[r][c] = hs[(size_t)(row0 + r) * HH + c];
            sW[r][c] = W[i];
        }
        __syncthreads();
        int ty = tid >> 4, tx = tid & 15;
        float acc[4][4] = {};
#pragma unroll 8
        for (int k = 0; k < 64; k++) {
            float a[4], bv[4];
#pragma unroll
            for (int i = 0; i < 4; i++) a[i] = sH[ty * 4 + i][k];
#pragma unroll
            for (int j = 0; j < 4; j++) bv[j] = sW[tx * 4 + j][k];
#pragma unroll
            for (int i = 0; i < 4; i++)
#pragma unroll
                for (int j = 0; j < 4; j++)
                    acc[i][j] = fmaf(a[i], bv[j], acc[i][j]);
        }
        float ss[4];
#pragma unroll
        for (int i = 0; i < 4; i++)
            ss[i] = acc[i][0]*acc[i][0] + acc[i][1]*acc[i][1]
                  + acc[i][2]*acc[i][2] + acc[i][3]*acc[i][3];
#pragma unroll
        for (int off = 8; off >= 1; off >>= 1)
#pragma unroll
            for (int i = 0; i < 4; i++)
                ss[i] += __shfl_xor_sync(0xffffffffu, ss[i], off);
#pragma unroll
        for (int i = 0; i < 4; i++) {
            float inv = rsqrtf(ss[i]);
#pragma unroll
            for (int j = 0; j < 4; j++)
                dst[(size_t)(row0 + ty * 4 + i) * HH + tx * 4 + j] =
                    __float2bfloat16(acc[i][j] * inv);
        }
        return;
    }
    {
        int p = blk - PRE_MASK - PRE_PROJ;
        int tt = p >> 9;
        int idx = ((p & 511) << 8) + tid;
        const float* src = (tt == 0) ? h0 : (tt == 1 ? h1 : h2);
        __nv_bfloat16* dst = g_v[tt];
        float4 v = ((const float4*)src)[idx];
        ((__nv_bfloat162*)dst)[idx * 2]     = __floats2bfloat162_rn(v.x, v.y);
        ((__nv_bfloat162*)dst)[idx * 2 + 1] = __floats2bfloat162_rn(v.z, v.w);
        ((float4*)g_acc[tt])[idx] = make_float4(0.f, 0.f, 0.f, 0.f);
    }
}

// ============================================================
// Kernel B: masked cosine attention, mma.sync m16n8k16 bf16
// R15 structure; NEW epilogue: raw masked-S via AND-mask (no per-element
// scaling); 1/cnt applied as edge-boundary ratio + final scale on O.
// ============================================================
#define LDS_PAD 72
#define KVOFF_H (128*LDS_PAD)
#define BUF_STRIDE_H (2*64*LDS_PAD)
#define ATTN_SMEM ((KVOFF_H + 3*BUF_STRIDE_H) * 2)   // 73728 B

#define LDSM_X4(r0,r1,r2,r3,addr) \
    asm volatile("ldmatrix.sync.aligned.m8n8.x4.shared.b16 {%0,%1,%2,%3}, [%4];" \
        : "=r"(r0), "=r"(r1), "=r"(r2), "=r"(r3) : "r"(addr))
#define LDSM_X4_T(r0,r1,r2,r3,addr) \
    asm volatile("ldmatrix.sync.aligned.m8n8.x4.trans.shared.b16 {%0,%1,%2,%3}, [%4];" \
        : "=r"(r0), "=r"(r1), "=r"(r2), "=r"(r3) : "r"(addr))
#define MMA16816(c, a, b0, b1) \
    asm volatile("mma.sync.aligned.m16n8k16.row.col.f32.bf16.bf16.f32 " \
        "{%0,%1,%2,%3}, {%4,%5,%6,%7}, {%8,%9}, {%0,%1,%2,%3};" \
        : "+f"((c)[0]), "+f"((c)[1]), "+f"((c)[2]), "+f"((c)[3]) \
        : "r"((a)[0]), "r"((a)[1]), "r"((a)[2]), "r"((a)[3]), "r"(b0), "r"(b1))
#define CP_ASYNC16(dst, src) \
    asm volatile("cp.async.cg.shared.global [%0], [%1], 16;" :: "r"(dst), "l"(src))
#define CP_COMMIT() asm volatile("cp.async.commit_group;" ::: "memory")
#define CP_WAIT(n)  asm volatile("cp.async.wait_group %0;" :: "n"(n) : "memory")

#define VPRED(e) ((0x948 >> (2 * (e))) & 3)   // {0,2,0,1,1,2}

__global__ void __launch_bounds__(128, 3) attn_mma_kernel() {
    extern __shared__ __align__(16) __nv_bfloat16 smh[];
    int tid = threadIdx.x, warp = tid >> 5, lane = tid & 31;
    int g = lane >> 2, tig = lane & 3;
    int t = blockIdx.z >> 1, b = blockIdx.z & 1;
    int split = blockIdx.y;
    int row0 = blockIdx.x * 128;

    uint32_t sQb = smem_u32(smh);
    uint32_t sKVb = sQb + KVOFF_H * 2;

    const __nv_bfloat16* qg = g_qnb[t] + ((size_t)b * NN + row0) * HH;
#pragma unroll
    for (int i = 0; i < 8; i++) {
        int idx = i * 128 + tid;
        int r = idx >> 3, c = idx & 7;
        *(uint4*)&smh[r * LDS_PAD + c * 8] = *(const uint4*)&qg[r * HH + c * 8];
    }
    __syncthreads();

    uint32_t qa[2][4][4];
    {
        int qcol = (lane >> 4) << 3;
#pragma unroll
        for (int rb = 0; rb < 2; rb++) {
            int qrow = warp * 32 + rb * 16 + (lane & 15);
#pragma unroll
            for (int kc = 0; kc < 4; kc++) {
                uint32_t addr = sQb + (uint32_t)(qrow * LDS_PAD + kc * 16 + qcol) * 2;
                LDSM_X4(qa[rb][kc][0], qa[rb][kc][1], qa[rb][kc][2], qa[rb][kc][3], addr);
            }
        }
    }

    int rowA[2], rowB[2];
#pragma unroll
    for (int rb = 0; rb < 2; rb++) {
        rowA[rb] = row0 + warp * 32 + rb * 16 + g;
        rowB[rb] = rowA[rb] + 8;
    }

    float invA[2][2], invB[2][2];
#pragma unroll
    for (int eh = 0; eh < 2; eh++) {
        int e = 2 * t + eh;
#pragma unroll
        for (int rb = 0; rb < 2; rb++) {
            invA[eh][rb] = g_inv[e][rowA[rb]];
            invB[eh][rb] = g_inv[e][rowB[rb]];
        }
    }

    auto stage = [&](int tile, int buf) {
        int e2 = 2 * t + (tile >> 4);
        size_t toff = (size_t)b * NN * HH + (size_t)(split * 16 + (tile & 15)) * 64 * HH;
        const __nv_bfloat16* kg = g_knb[e2] + toff;
        const __nv_bfloat16* vg = g_v[VPRED(e2)] + toff;
        uint32_t kb = sKVb + (uint32_t)buf * (BUF_STRIDE_H * 2);
        uint32_t vb = kb + (uint32_t)(64 * LDS_PAD * 2);
#pragma unroll
        for (int i = 0; i < 4; i++) {
            int idx = i * 128 + tid;
            int r = idx >> 3, c = (idx & 7) * 8;
            uint32_t so = (uint32_t)(r * LDS_PAD + c) * 2;
            CP_ASYNC16(kb + so, kg + r * HH + c);
            CP_ASYNC16(vb + so, vg + r * HH + c);
        }
        CP_COMMIT();
    };

    stage(0, 0);
    stage(1, 1);

    float o[2][8][4] = {};
    int k0 = (tig & 1) * 2;
    int shbase0 = tig >> 1;

    for (int it = 0; it < 32; it++) {
        int eh = it >> 4;
        int e = 2 * t + eh;
        int kt = split * 16 + (it & 15);
        int c4 = (kt >> 1) * 4;
        int shb = shbase0 + ((kt & 1) << 4);
        uint32_t mEA[2], mOA[2], mEB[2], mOB[2];
#pragma unroll
        for (int rb = 0; rb < 2; rb++) {
            mEA[rb] = g_mbits[e][c4 + k0][rowA[rb]];
            mOA[rb] = g_mbits[e][c4 + k0 + 1][rowA[rb]];
            mEB[rb] = g_mbits[e][c4 + k0][rowB[rb]];
            mOB[rb] = g_mbits[e][c4 + k0 + 1][rowB[rb]];
        }

        // edge boundary: fold edge-0's inv into O as a ratio (once)
        if (it == 16) {
#pragma unroll
            for (int rb = 0; rb < 2; rb++) {
                float rA = invA[0][rb] / invA[1][rb];
                float rB = invB[0][rb] / invB[1][rb];
#pragma unroll
                for (int nt = 0; nt < 8; nt++) {
                    o[rb][nt][0] *= rA; o[rb][nt][1] *= rA;
                    o[rb][nt][2] *= rB; o[rb][nt][3] *= rB;
                }
            }
        }

        if (it < 31) CP_WAIT(1); else CP_WAIT(0);
        __syncthreads();
        if (it + 2 < 32) stage(it + 2, (it + 2) % 3);

        uint32_t kb = sKVb + (uint32_t)(it % 3) * (BUF_STRIDE_H * 2);
        uint32_t vb = kb + (uint32_t)(64 * LDS_PAD * 2);

        int krow_off = ((lane >> 4) << 3) + (lane & 7);
        int kcol_off = ((lane >> 3) & 1) << 3;

        // ---- per 32-key half: S (2 jp) -> AND-mask epilogue -> PV ----
#pragma unroll
        for (int jph = 0; jph < 2; jph++) {
            uint32_t pa[2][2][4];
#pragma unroll
            for (int jj2 = 0; jj2 < 2; jj2++) {
                int jp = 2 * jph + jj2;
                float s2[2][2][4] = {};
#pragma unroll
                for (int kc = 0; kc < 4; kc++) {
                    uint32_t b0, b1, b2, b3;
                    uint32_t addr = kb + (uint32_t)((16 * jp + krow_off) * LDS_PAD
                                                     + kc * 16 + kcol_off) * 2;
                    LDSM_X4(b0, b1, b2, b3, addr);
#pragma unroll
                    for (int rb = 0; rb < 2; rb++) {
                        MMA16816(s2[rb][0], qa[rb][kc], b0, b1);
                        MMA16816(s2[rb][1], qa[rb][kc], b2, b3);
                    }
                }
#pragma unroll
                for (int rb = 0; rb < 2; rb++) {
#pragma unroll
                    for (int jj = 0; jj < 2; jj++) {
                        int j = 2 * jp + jj;
                        int sh = shb + 2 * j;
                        uint32_t mskA = (((mEA[rb] >> sh) & 1u) * 0x0000FFFFu)
                                      | (((mOA[rb] >> sh) & 1u) * 0xFFFF0000u);
                        uint32_t mskB = (((mEB[rb] >> sh) & 1u) * 0x0000FFFFu)
                                      | (((mOB[rb] >> sh) & 1u) * 0xFFFF0000u);
                        uint32_t p01, p23;
                        asm("cvt.rn.bf16x2.f32 %0, %1, %2;"
                            : "=r"(p01) : "f"(s2[rb][jj][1]), "f"(s2[rb][jj][0]));
                        asm("cvt.rn.bf16x2.f32 %0, %1, %2;"
                            : "=r"(p23) : "f"(s2[rb][jj][3]), "f"(s2[rb][jj][2]));
                        pa[rb][jj2][jj * 2]     = p01 & mskA;
                        pa[rb][jj2][jj * 2 + 1] = p23 & mskB;
                    }
                }
            }
#pragma unroll
            for (int nt = 0; nt < 8; nt++) {
                uint32_t b0, b1, b2, b3;
                uint32_t addr = vb + (uint32_t)((32 * jph + lane) * LDS_PAD + nt * 8) * 2;
                LDSM_X4_T(b0, b1, b2, b3, addr);
#pragma unroll
                for (int rb = 0; rb < 2; rb++) {
                    MMA16816(o[rb][nt], pa[rb][0], b0, b1);
                    MMA16816(o[rb][nt], pa[rb][1], b2, b3);
                }
            }
        }
    }

    // ---- final scale by edge-1 inv, then accumulate into g_acc ----
    float* dst = g_acc[t] + (size_t)b * NN * HH;
#pragma unroll
    for (int rb = 0; rb < 2; rb++) {
        float iA = invA[1][rb], iB = invB[1][rb];
#pragma unroll
        for (int nt = 0; nt < 8; nt++) {
            int col = nt * 8 + 2 * tig;
            atomicAdd(&dst[(size_t)rowA[rb] * HH + col],     o[rb][nt][0] * iA);
            atomicAdd(&dst[(size_t)rowA[rb] * HH + col + 1], o[rb][nt][1] * iA);
            atomicAdd(&dst[(size_t)rowB[rb] * HH + col],     o[rb][nt][2] * iB);
            atomicAdd(&dst[(size_t)rowB[rb] * HH + col + 1], o[rb][nt][3] * iB);
        }
    }
}

// ============================================================
// Kernel C: gated Euler update + outputs (fp32, unchanged)
// ============================================================
__global__ void update_kernel(const float* __restrict__ x0,
                              const float* __restrict__ h0,
                              const float* __restrict__ h1,
                              const float* __restrict__ h2,
                              const float* __restrict__ Wsu0,
                              const float* __restrict__ Wsu12,
                              const float* __restrict__ Wdt,
                              const float* __restrict__ bdt,
                              const float* __restrict__ stepp,
                              const float* __restrict__ oscale,
                              float* __restrict__ out2,
                              float* __restrict__ outh0,
                              float* __restrict__ outh1,
                              float* __restrict__ outh2) {
    extern __shared__ float sm[];
    float* sH = sm;               // [64][65]
    float* sW = sm + 64 * 65;     // [64][97]
    float* sA = sW + 64 * 97;     // [64][97]
    int t = blockIdx.y;
    int row0 = blockIdx.x * 64;
    int tid = threadIdx.x, ty = tid >> 4, tx = tid & 15;

    const float* hs = (t == 0) ? h0 : (t == 1 ? h1 : h2);
    float* outh = (t == 0) ? outh0 : (t == 1 ? outh1 : outh2);
    const float* Wd = Wdt + t * HH * HH;

    for (int i = tid; i < 64 * 64; i += 256) {
        int r = i >> 6, c = i & 63;
        sH[r * 65 + c] = hs[(size_t)(row0 + r) * HH + c];
        sW[r * 97 + c] = Wd[i];
    }
    __syncthreads();

    float z[4][4];
#pragma unroll
    for (int j = 0; j < 4; j++) {
        float bj = __ldg(&bdt[t * 64 + tx * 4 + j]);
#pragma unroll
        for (int i = 0; i < 4; i++) z[i][j] = bj;
    }
#pragma unroll 8
    for (int k = 0; k < 64; k++) {
        float a[4], bv[4];
#pragma unroll
        for (int i = 0; i < 4; i++) a[i] = sH[(ty * 4 + i) * 65 + k];
#pragma unroll
        for (int j = 0; j < 4; j++) bv[j] = sW[(tx * 4 + j) * 97 + k];
#pragma unroll
        for (int i = 0; i < 4; i++)
#pragma unroll
            for (int j = 0; j < 4; j++)
                z[i][j] = fmaf(a[i], bv[j], z[i][j]);
    }
    float dtv[4][4];
#pragma unroll
    for (int i = 0; i < 4; i++)
#pragma unroll
        for (int j = 0; j < 4; j++)
            dtv[i][j] = 2.0f / (1.0f + expf(-z[i][j])) - 1.0f;
    __syncthreads();

    int Ksu = (t == 0) ? (INDIM + HH) : HH;
    const float* Ws = (t == 0) ? Wsu0 : (Wsu12 + (t - 1) * HH * HH);
    const float* acc = g_acc[t];
    for (int i = tid; i < 64 * Ksu; i += 256) {
        int r = i / Ksu, c = i - r * Ksu;
        sW[r * 97 + c] = Ws[i];
        float av;
        if (t == 0) {
            if (c < INDIM) av = x0[(size_t)(row0 + r) * INDIM + c];
            else           av = acc[(size_t)(row0 + r) * HH + (c - INDIM)];
        } else {
            av = acc[(size_t)(row0 + r) * HH + c];
        }
        sA[r * 97 + c] = av;
    }
    __syncthreads();

    float su[4][4] = {};
#pragma unroll 8
    for (int k = 0; k < Ksu; k++) {
        float a[4], bv[4];
#pragma unroll
        for (int i = 0; i < 4; i++) a[i] = sA[(ty * 4 + i) * 97 + k];
#pragma unroll
        for (int j = 0; j < 4; j++) bv[j] = sW[(tx * 4 + j) * 97 + k];
#pragma unroll
        for (int i = 0; i < 4; i++)
#pragma unroll
            for (int j = 0; j < 4; j++)
                su[i][j] = fmaf(a[i], bv[j], su[i][j]);
    }

    float stepv = *stepp;
    float osc = *oscale;
#pragma unroll
    for (int i = 0; i < 4; i++) {
        int r = row0 + ty * 4 + i;
#pragma unroll
        for (int j = 0; j < 4; j++) {
            int c = tx * 4 + j;
            float hv = sH[(ty * 4 + i) * 65 + c];
            float hn = fmaf(stepv * dtv[i][j], su[i][j], hv);
            outh[(size_t)r * HH + c] = hn;
            if (t == 2 && c < OUTDIM)
                out2[(size_t)r * OUTDIM + c] = osc * hn;
        }
    }
}

// ============================================================
extern "C" void kernel_launch(void* const* d_in, const int* in_sizes, int n_in,
                              void* d_out, int out_size) {
    const float* x0  = (const float*)d_in[0];
    const float* h0  = (const float*)d_in[1];
    const float* h1  = (const float*)d_in[2];
    const float* h2  = (const float*)d_in[3];
    const float* m00 = (const float*)d_in[4];
    const float* m20 = (const float*)d_in[5];
    const float* m01 = (const float*)d_in[6];
    const float* m11 = (const float*)d_in[7];
    const float* m12 = (const float*)d_in[8];
    const float* m22 = (const float*)d_in[9];
    const float* Wq    = (const float*)d_in[10];
    const float* Wk    = (const float*)d_in[11];
    const float* Wsu0  = (const float*)d_in[12];
    const float* Wsu12 = (const float*)d_in[13];
    const float* Wdt   = (const float*)d_in[14];
    const float* bdt   = (const float*)d_in[15];
    const float* stepp = (const float*)d_in[16];
    const float* oscal = (const float*)d_in[17];

    float* out2 = (float*)d_out;
    float* h0n = out2 + (size_t)BB * NN * OUTDIM;
    float* h1n = h0n + (size_t)BB * NN * HH;
    float* h2n = h1n + (size_t)BB * NN * HH;

    const int UPD_SMEM = (64 * 65 + 2 * 64 * 97) * 4;
    cudaFuncSetAttribute(attn_mma_kernel, cudaFuncAttributeMaxDynamicSharedMemorySize, ATTN_SMEM);
    cudaFuncSetAttribute(update_kernel, cudaFuncAttributeMaxDynamicSharedMemorySize, UPD_SMEM);

    pre_kernel<<<PRE_MASK + PRE_PROJ + PRE_CONV, 256>>>(h0, h1, h2, Wq, Wk,
                                                        m00, m20, m01, m11, m12, m22);
    attn_mma_kernel<<<dim3(NN / 128, NSPLIT, 6), 128, ATTN_SMEM>>>();
    update_kernel<<<dim3(ROWS / 64, 3), 256, UPD_SMEM>>>(x0, h0, h1, h2,
                                                         Wsu0, Wsu12, Wdt, bdt,
                                                         stepp, oscal,
                                                         out2, h0n, h1n, h2n);
}